// round 1
// baseline (speedup 1.0000x reference)
#include <cuda_runtime.h>

#define NUM_INPUT  700
#define NUM_HIDDEN 256
#define NUM_OUTPUT 20
#define WIN        50
#define BATCH      512
#define THRESH     0.3f
#define ALPHA      0.8f

#define M_ROWS (BATCH * WIN)   // 25600

// ---------------- device scratch (allowed: __device__ globals) ----------------
__device__ float g_WcT[3 * NUM_INPUT * NUM_HIDDEN];      // [i][k][h] combined Wf0 @ Wd[i], transposed
__device__ float g_WfT[2 * NUM_HIDDEN * NUM_HIDDEN];     // [l][k][h]
__device__ float g_WrT[2 * NUM_HIDDEN * NUM_HIDDEN];     // [l][k][h]
__device__ float g_WoT[NUM_HIDDEN * NUM_OUTPUT];         // [k][o]
__device__ float g_cvec[NUM_HIDDEN];                     // bf0 + (sum_i bd_i) @ Wf0^T
__device__ float g_ff0[M_ROWS * NUM_HIDDEN];             // [b*50+t][h] = cur@Wf0^T + bias

// ---------------- prep kernels ----------------
__global__ void prep_transpose(const float* __restrict__ Wf,
                               const float* __restrict__ Wr,
                               const float* __restrict__ Wo) {
    int idx = blockIdx.x * 256 + threadIdx.x;
    if (idx < 2 * 256 * 256) {
        int h = idx & 255;
        int k = (idx >> 8) & 255;
        int l = idx >> 16;
        g_WfT[(l * 256 + k) * 256 + h] = Wf[(l * 256 + h) * 256 + k];
        g_WrT[(l * 256 + k) * 256 + h] = Wr[(l * 256 + h) * 256 + k];
    }
    if (idx < 256 * 20) {
        int o = idx % 20;
        int k = idx / 20;
        g_WoT[k * 20 + o] = Wo[o * 256 + k];
    }
}

// WcT[i][k][h] = sum_j Wf0[h][j] * Wd[i][j][k]   (uses g_WfT[0] for coalescing)
__global__ void prep_wc(const float* __restrict__ Wd) {
    int ik = blockIdx.x;          // 0 .. 3*700-1
    int i = ik / NUM_INPUT;
    int k = ik % NUM_INPUT;
    int h = threadIdx.x;
    float s = 0.f;
#pragma unroll 8
    for (int j = 0; j < 256; j++) {
        s += g_WfT[j * 256 + h] * __ldg(&Wd[(i * 256 + j) * NUM_INPUT + k]);
    }
    g_WcT[(i * NUM_INPUT + k) * 256 + h] = s;
}

// cvec[h] = bf0[h] + sum_j (bd0+bd1+bd2)[j] * Wf0[h][j]
__global__ void prep_cvec(const float* __restrict__ bd, const float* __restrict__ bf) {
    int h = threadIdx.x;
    float s = bf[h];
#pragma unroll 8
    for (int j = 0; j < 256; j++) {
        float bsum = bd[j] + bd[256 + j] + bd[512 + j];
        s += bsum * g_WfT[j * 256 + h];
    }
    g_cvec[h] = s;
}

// ---------------- ff0 GEMM: ff0[row][h] = sum_i x_shift_i[row] @ WcT[i] + cvec ----------------
// M=25600, N=256, K=700 x 3 delays.  BM=128, BN=64, BK=16, 256 threads, 8x4 microtile.
#define GA_BM 128
#define GA_BN 64
#define GA_BK 16

__global__ __launch_bounds__(256) void gemm_ff0(const float* __restrict__ x) {
    __shared__ float As[GA_BK][GA_BM + 4];
    __shared__ float Bs[GA_BK][GA_BN];

    const int tid = threadIdx.x;
    const int rowBase = blockIdx.y * GA_BM;
    const int colBase = blockIdx.x * GA_BN;
    const int tx = tid & 15;       // col group
    const int ty = tid >> 4;       // row group

    float acc[8][4];
#pragma unroll
    for (int i = 0; i < 8; i++)
#pragma unroll
        for (int j = 0; j < 4; j++) acc[i][j] = 0.f;

    const int delays[3] = {0, 16, 32};

    const int mm = tid >> 2;            // 0..63
    const int kq = (tid & 3) * 4;       // 0,4,8,12
    const int kkB = tid >> 4;           // 0..15
    const int hhB = (tid & 15) * 4;

    for (int i = 0; i < 3; i++) {
        const int d = delays[i];
        const float* __restrict__ Bsrc = &g_WcT[i * NUM_INPUT * 256];

        for (int kb = 0; kb < 704; kb += GA_BK) {
            // ---- load A tile (128 x 16), two halves of 64 rows ----
            int kg = kb + kq;
            bool kvalid = (kg < NUM_INPUT);
#pragma unroll
            for (int half = 0; half < 2; half++) {
                int r = rowBase + mm + half * 64;
                int b = r / WIN;
                int t = r - b * WIN;
                int ts = t - d;
                float4 v = make_float4(0.f, 0.f, 0.f, 0.f);
                if (ts >= 0 && kvalid)
                    v = *reinterpret_cast<const float4*>(x + (b * WIN + ts) * NUM_INPUT + kg);
                As[kq + 0][mm + half * 64] = v.x;
                As[kq + 1][mm + half * 64] = v.y;
                As[kq + 2][mm + half * 64] = v.z;
                As[kq + 3][mm + half * 64] = v.w;
            }
            // ---- load B tile (16 x 64) ----
            int kg2 = kb + kkB;
            float4 w = make_float4(0.f, 0.f, 0.f, 0.f);
            if (kg2 < NUM_INPUT)
                w = *reinterpret_cast<const float4*>(Bsrc + kg2 * 256 + colBase + hhB);
            *reinterpret_cast<float4*>(&Bs[kkB][hhB]) = w;

            __syncthreads();

#pragma unroll
            for (int kk = 0; kk < GA_BK; kk++) {
                float4 a0 = *reinterpret_cast<const float4*>(&As[kk][ty * 8 + 0]);
                float4 a1 = *reinterpret_cast<const float4*>(&As[kk][ty * 8 + 4]);
                float4 bb = *reinterpret_cast<const float4*>(&Bs[kk][tx * 4]);
                float av[8] = {a0.x, a0.y, a0.z, a0.w, a1.x, a1.y, a1.z, a1.w};
                float bv[4] = {bb.x, bb.y, bb.z, bb.w};
#pragma unroll
                for (int ii = 0; ii < 8; ii++)
#pragma unroll
                    for (int jj = 0; jj < 4; jj++) acc[ii][jj] += av[ii] * bv[jj];
            }
            __syncthreads();
        }
    }

    // epilogue: + cvec
#pragma unroll
    for (int ii = 0; ii < 8; ii++) {
        int r = rowBase + ty * 8 + ii;
#pragma unroll
        for (int jj = 0; jj < 4; jj++) {
            int c = colBase + tx * 4 + jj;
            g_ff0[r * 256 + c] = acc[ii][jj] + g_cvec[c];
        }
    }
}

// ---------------- recurrent scan ----------------
// 64 blocks x 256 threads; each block owns 8 batch rows for all 50 steps.
// Thread = hidden unit h. Spikes kept as 8-bit row masks per column in smem.
__global__ __launch_bounds__(256) void scan_kernel(const float* __restrict__ bf,
                                                   const float* __restrict__ bo,
                                                   float* __restrict__ out) {
    const int h = threadIdx.x;
    const int b0 = blockIdx.x * 8;

    __shared__ unsigned int mask0[256];   // s0 column masks (bit r = row r)
    __shared__ unsigned int mask1[256];   // s1 column masks
    __shared__ float osm[8][20];
    __shared__ float otmp[8][20];
    __shared__ float orow_max[8];
    __shared__ float orow_sum[8];

    float m0[8], m1[8];
#pragma unroll
    for (int r = 0; r < 8; r++) { m0[r] = 0.f; m1[r] = 0.f; }
    unsigned int myS0 = 0, myS1 = 0;

    // output-layer state (threads 0..159: row=h/20, col=h%20)
    const bool isO = (h < 160);
    const int orow = h / 20;
    const int ocol = h - orow * 20;
    float o_mem = 0.f, o_sumv = 0.f, o_mot = 0.f;
    unsigned int o_spk = 0;

    const float bf1 = bf[256 + h];
    const float bov = isO ? bo[ocol] : 0.f;

    mask0[h] = 0;
    mask1[h] = 0;
    __syncthreads();

    for (int t = 0; t < WIN; t++) {
        // ================= layer 0 =================
        float acc[8];
#pragma unroll
        for (int r = 0; r < 8; r++)
            acc[r] = g_ff0[((b0 + r) * WIN + t) * 256 + h];

        // recurrent: + s0_old @ Wr0^T
        const float* __restrict__ wr0 = &g_WrT[0];
        for (int k = 0; k < 256; k++) {
            unsigned int mk = mask0[k];
            if (mk) {
                float w = __ldg(&wr0[k * 256 + h]);
#pragma unroll
                for (int r = 0; r < 8; r++)
                    if (mk & (1u << r)) acc[r] += w;
            }
        }
        unsigned int ns = 0;
#pragma unroll
        for (int r = 0; r < 8; r++) {
            float dm = (myS0 >> r) & 1u ? 0.f : ALPHA;
            m0[r] = m0[r] * dm + acc[r];
            if (m0[r] - THRESH > 0.f) ns |= (1u << r);
        }
        __syncthreads();             // everyone done reading old mask0
        mask0[h] = ns;
        myS0 = ns;
        __syncthreads();

        // ================= layer 1 =================
#pragma unroll
        for (int r = 0; r < 8; r++) acc[r] = bf1;

        const float* __restrict__ wf1 = &g_WfT[256 * 256];
        for (int k = 0; k < 256; k++) {
            unsigned int mk = mask0[k];          // s0 NEW
            if (mk) {
                float w = __ldg(&wf1[k * 256 + h]);
#pragma unroll
                for (int r = 0; r < 8; r++)
                    if (mk & (1u << r)) acc[r] += w;
            }
        }
        const float* __restrict__ wr1 = &g_WrT[256 * 256];
        for (int k = 0; k < 256; k++) {
            unsigned int mk = mask1[k];          // s1 OLD
            if (mk) {
                float w = __ldg(&wr1[k * 256 + h]);
#pragma unroll
                for (int r = 0; r < 8; r++)
                    if (mk & (1u << r)) acc[r] += w;
            }
        }
        ns = 0;
#pragma unroll
        for (int r = 0; r < 8; r++) {
            float dm = (myS1 >> r) & 1u ? 0.f : ALPHA;
            m1[r] = m1[r] * dm + acc[r];
            if (m1[r] - THRESH > 0.f) ns |= (1u << r);
        }
        __syncthreads();             // everyone done reading old mask1
        mask1[h] = ns;
        myS1 = ns;
        __syncthreads();

        // ================= output layer =================
        if (isO) {
            float oa = bov;
            unsigned int bit = 1u << orow;
            for (int k = 0; k < 256; k++) {
                if (mask1[k] & bit) oa += __ldg(&g_WoT[k * 20 + ocol]);
            }
            float dm = o_spk ? 0.f : ALPHA;
            o_mem = o_mem * dm + oa;
            o_spk = (o_mem - THRESH > 0.f) ? 1u : 0u;
            if (o_spk) o_sumv += 1.f;
            osm[orow][ocol] = o_mem;
        }
        __syncthreads();
        if (h < 8) {
            float mx = -1e30f;
#pragma unroll
            for (int o = 0; o < 20; o++) mx = fmaxf(mx, osm[h][o]);
            orow_max[h] = mx;
        }
        __syncthreads();
        if (isO) {
            float e = expf(o_mem - orow_max[orow]);
            otmp[orow][ocol] = e;
        }
        __syncthreads();
        if (h < 8) {
            float s = 0.f;
#pragma unroll
            for (int o = 0; o < 20; o++) s += otmp[h][o];
            orow_sum[h] = s;
        }
        __syncthreads();
        if (isO) {
            o_mot += otmp[orow][ocol] / orow_sum[orow];
        }
        __syncthreads();
    }

    if (isO) {
        int b = b0 + orow;
        out[b * 20 + ocol] = o_sumv / (float)WIN;                 // o_sum / win
        out[BATCH * 20 + b * 20 + ocol] = o_mot;                  // out_mot
    }
}

// ---------------- launch ----------------
extern "C" void kernel_launch(void* const* d_in, const int* in_sizes, int n_in,
                              void* d_out, int out_size) {
    const float* x  = (const float*)d_in[0];
    const float* Wd = (const float*)d_in[1];
    const float* bd = (const float*)d_in[2];
    const float* Wf = (const float*)d_in[3];
    const float* bf = (const float*)d_in[4];
    const float* Wr = (const float*)d_in[5];
    const float* Wo = (const float*)d_in[6];
    const float* bo = (const float*)d_in[7];
    float* out = (float*)d_out;

    prep_transpose<<<512, 256>>>(Wf, Wr, Wo);
    prep_wc<<<3 * NUM_INPUT, 256>>>(Wd);
    prep_cvec<<<1, 256>>>(bd, bf);
    gemm_ff0<<<dim3(NUM_HIDDEN / GA_BN, M_ROWS / GA_BM), 256>>>(x);
    scan_kernel<<<64, 256>>>(bf, bo, out);
}

// round 2
// speedup vs baseline: 2.0739x; 2.0739x over previous
#include <cuda_runtime.h>

#define NUM_INPUT  700
#define NUM_HIDDEN 256
#define NUM_OUTPUT 20
#define WIN        50
#define BATCH      512
#define THRESH     0.3f
#define ALPHA      0.8f

#define M_ROWS (BATCH * WIN)   // 25600

// ---------------- device scratch ----------------
__device__ float g_WcT[3 * NUM_INPUT * NUM_HIDDEN];      // [i][k][h] combined Wf0 @ Wd[i], transposed
__device__ float g_WfT[2 * NUM_HIDDEN * NUM_HIDDEN];     // [l][k][h]
__device__ float g_WrT[2 * NUM_HIDDEN * NUM_HIDDEN];     // [l][k][h]
__device__ float g_WoT[NUM_HIDDEN * NUM_OUTPUT];         // [k][o]
__device__ float g_cvec[NUM_HIDDEN];                     // bf0 + (sum_i bd_i) @ Wf0^T
__device__ float g_ff0[M_ROWS * NUM_HIDDEN];             // [b*50+t][h]

// ---------------- prep kernels ----------------
__global__ void prep_transpose(const float* __restrict__ Wf,
                               const float* __restrict__ Wr,
                               const float* __restrict__ Wo) {
    int idx = blockIdx.x * 256 + threadIdx.x;
    if (idx < 2 * 256 * 256) {
        int h = idx & 255;
        int k = (idx >> 8) & 255;
        int l = idx >> 16;
        g_WfT[(l * 256 + k) * 256 + h] = Wf[(l * 256 + h) * 256 + k];
        g_WrT[(l * 256 + k) * 256 + h] = Wr[(l * 256 + h) * 256 + k];
    }
    if (idx < 256 * 20) {
        int o = idx % 20;
        int k = idx / 20;
        g_WoT[k * 20 + o] = Wo[o * 256 + k];
    }
}

__global__ void prep_wc(const float* __restrict__ Wd) {
    int ik = blockIdx.x;          // 0 .. 3*700-1
    int i = ik / NUM_INPUT;
    int k = ik % NUM_INPUT;
    int h = threadIdx.x;
    float s = 0.f;
#pragma unroll 8
    for (int j = 0; j < 256; j++) {
        s += g_WfT[j * 256 + h] * __ldg(&Wd[(i * 256 + j) * NUM_INPUT + k]);
    }
    g_WcT[(i * NUM_INPUT + k) * 256 + h] = s;
}

__global__ void prep_cvec(const float* __restrict__ bd, const float* __restrict__ bf) {
    int h = threadIdx.x;
    float s = bf[h];
#pragma unroll 8
    for (int j = 0; j < 256; j++) {
        float bsum = bd[j] + bd[256 + j] + bd[512 + j];
        s += bsum * g_WfT[j * 256 + h];
    }
    g_cvec[h] = s;
}

// ---------------- ff0 GEMM: M=25600, N=256, K=700 x 3 delays ----------------
// BM=128, BN=128, BK=8, 256 threads, 8x8 microtile.
#define GB_BM 128
#define GB_BN 128
#define GB_BK 8

__global__ __launch_bounds__(256) void gemm_ff0(const float* __restrict__ x) {
    __shared__ float As[GB_BK][GB_BM + 4];
    __shared__ float Bs[GB_BK][GB_BN];

    const int tid = threadIdx.x;
    const int rowBase = blockIdx.y * GB_BM;
    const int colBase = blockIdx.x * GB_BN;
    const int ty = tid >> 4;       // 0..15 -> rows ty*8..
    const int tx = tid & 15;       // 0..15 -> cols tx*8..

    float acc[8][8];
#pragma unroll
    for (int i = 0; i < 8; i++)
#pragma unroll
        for (int j = 0; j < 8; j++) acc[i][j] = 0.f;

    const int delays[3] = {0, 16, 32};

    // A-load mapping: thread loads 4 consecutive k for one row
    const int arow = tid >> 1;            // 0..127
    const int akq  = (tid & 1) * 4;       // 0 or 4
    // B-load mapping
    const int bk   = tid >> 5;            // 0..7
    const int bco  = (tid & 31) * 4;      // 0..124

    const int gr = rowBase + arow;
    const int gb = gr / WIN;
    const int gt = gr - gb * WIN;

    for (int i = 0; i < 3; i++) {
        const int d = delays[i];
        const float* __restrict__ Bsrc = &g_WcT[i * NUM_INPUT * 256];
        const int ts = gt - d;
        const float* __restrict__ arp = (ts >= 0) ? (x + (gb * WIN + ts) * NUM_INPUT) : 0;

        for (int kb = 0; kb < 704; kb += GB_BK) {
            int kg = kb + akq;
            float4 av = make_float4(0.f, 0.f, 0.f, 0.f);
            if (arp && kg < NUM_INPUT)
                av = *reinterpret_cast<const float4*>(arp + kg);
            As[akq + 0][arow] = av.x;
            As[akq + 1][arow] = av.y;
            As[akq + 2][arow] = av.z;
            As[akq + 3][arow] = av.w;

            int kg2 = kb + bk;
            float4 bv = make_float4(0.f, 0.f, 0.f, 0.f);
            if (kg2 < NUM_INPUT)
                bv = *reinterpret_cast<const float4*>(Bsrc + kg2 * 256 + colBase + bco);
            *reinterpret_cast<float4*>(&Bs[bk][bco]) = bv;

            __syncthreads();

#pragma unroll
            for (int kk = 0; kk < GB_BK; kk++) {
                float4 a0 = *reinterpret_cast<const float4*>(&As[kk][ty * 8 + 0]);
                float4 a1 = *reinterpret_cast<const float4*>(&As[kk][ty * 8 + 4]);
                float4 b0 = *reinterpret_cast<const float4*>(&Bs[kk][tx * 8 + 0]);
                float4 b1 = *reinterpret_cast<const float4*>(&Bs[kk][tx * 8 + 4]);
                float av8[8] = {a0.x, a0.y, a0.z, a0.w, a1.x, a1.y, a1.z, a1.w};
                float bv8[8] = {b0.x, b0.y, b0.z, b0.w, b1.x, b1.y, b1.z, b1.w};
#pragma unroll
                for (int ii = 0; ii < 8; ii++)
#pragma unroll
                    for (int jj = 0; jj < 8; jj++) acc[ii][jj] += av8[ii] * bv8[jj];
            }
            __syncthreads();
        }
    }

#pragma unroll
    for (int ii = 0; ii < 8; ii++) {
        int r = rowBase + ty * 8 + ii;
#pragma unroll
        for (int jj = 0; jj < 8; jj++) {
            int c = colBase + tx * 8 + jj;
            g_ff0[r * 256 + c] = acc[ii][jj] + g_cvec[c];
        }
    }
}

// ---------------- recurrent scan ----------------
// 128 blocks x 256 threads; each block owns 4 batch rows for all 50 steps.
// Spikes stored as float4 per column (broadcast LDS.128), branchless FFMA.
// smem caches leading columns of Wr0/Wf1 and all of WoT.
#define SCAN_R 4
#define WR0C 128    // cached cols of layer0 Wr^T
#define WF1C 48     // cached cols of layer1 Wf^T

// float offsets in dynamic smem
#define OFF_WR0C 0
#define OFF_WF1C (OFF_WR0C + WR0C * 256)          // 32768
#define OFF_WOT  (OFF_WF1C + WF1C * 256)          // 45056
#define OFF_SP0  (OFF_WOT + 256 * 20)             // 50176
#define OFF_SP1  (OFF_SP0 + 2 * 256 * 4)          // 52224
#define OFF_OPART (OFF_SP1 + 2 * 256 * 4)         // 54272
#define OFF_OSM   (OFF_OPART + 160)               // 54432
#define OFF_OTMP  (OFF_OSM + 80)                  // 54512
#define OFF_OMAX  (OFF_OTMP + 80)                 // 54592
#define OFF_OSUM  (OFF_OMAX + 4)                  // 54596
#define SCAN_SMEM_FLOATS (OFF_OSUM + 4)           // 54600 -> 218400 bytes

__global__ __launch_bounds__(256) void scan_kernel(const float* __restrict__ bf,
                                                   const float* __restrict__ bo,
                                                   float* __restrict__ out) {
    extern __shared__ float sm[];
    float* wr0c = sm + OFF_WR0C;
    float* wf1c = sm + OFF_WF1C;
    float* wot  = sm + OFF_WOT;
    float4* sp0 = reinterpret_cast<float4*>(sm + OFF_SP0);   // [2][256]
    float4* sp1 = reinterpret_cast<float4*>(sm + OFF_SP1);   // [2][256]
    float* opart = sm + OFF_OPART;
    float* osm   = sm + OFF_OSM;
    float* otmp  = sm + OFF_OTMP;
    float* omax  = sm + OFF_OMAX;
    float* osum  = sm + OFF_OSUM;

    const int h = threadIdx.x;
    const int b0 = blockIdx.x * SCAN_R;

    // ---- fill smem caches ----
    {
        const float4* s0 = reinterpret_cast<const float4*>(g_WrT);
        float4* d0 = reinterpret_cast<float4*>(wr0c);
        for (int i = h; i < WR0C * 256 / 4; i += 256) d0[i] = s0[i];
        const float4* s1 = reinterpret_cast<const float4*>(g_WfT + 65536);
        float4* d1 = reinterpret_cast<float4*>(wf1c);
        for (int i = h; i < WF1C * 256 / 4; i += 256) d1[i] = s1[i];
        const float4* s2 = reinterpret_cast<const float4*>(g_WoT);
        float4* d2 = reinterpret_cast<float4*>(wot);
        for (int i = h; i < 256 * 20 / 4; i += 256) d2[i] = s2[i];
    }
    sp0[0 * 256 + h] = make_float4(0.f, 0.f, 0.f, 0.f);
    sp0[1 * 256 + h] = make_float4(0.f, 0.f, 0.f, 0.f);
    sp1[0 * 256 + h] = make_float4(0.f, 0.f, 0.f, 0.f);
    sp1[1 * 256 + h] = make_float4(0.f, 0.f, 0.f, 0.f);
    __syncthreads();

    float4 m0 = make_float4(0.f, 0.f, 0.f, 0.f);
    float4 m1 = make_float4(0.f, 0.f, 0.f, 0.f);
    float4 s0 = make_float4(0.f, 0.f, 0.f, 0.f);
    float4 s1v = make_float4(0.f, 0.f, 0.f, 0.f);

    const float bf1 = bf[256 + h];

    // output-layer roles
    const int q = h >> 1;                 // for h<160: partial id 0..79
    const int phalf = h & 1;
    const int porow = q / 20, pocol = q - porow * 20;
    const int orow = h / 20, ocol = h - orow * 20;   // for h<80
    const float bov = (h < 80) ? bo[ocol] : 0.f;
    float o_mem = 0.f, o_spk = 0.f, o_sumv = 0.f, o_mot = 0.f;

    const float* __restrict__ wr0g = g_WrT;                 // layer0 Wr^T
    const float* __restrict__ wf1g = g_WfT + 65536;         // layer1 Wf^T
    const float* __restrict__ wr1g = g_WrT + 65536;         // layer1 Wr^T

    for (int t = 0; t < WIN; t++) {
        const int ri = t & 1;
        const int wi = 1 - ri;
        const float4* sp0_old = sp0 + ri * 256;
        float4*       sp0_new = sp0 + wi * 256;
        const float4* sp1_old = sp1 + ri * 256;
        float4*       sp1_new = sp1 + wi * 256;

        // ================= layer 0 =================
        float4 acc;
        {
            const float* f0 = g_ff0 + ((size_t)b0 * WIN + t) * 256 + h;
            acc.x = f0[0];
            acc.y = f0[WIN * 256];
            acc.z = f0[2 * WIN * 256];
            acc.w = f0[3 * WIN * 256];
        }
#pragma unroll 8
        for (int k = 0; k < WR0C; k++) {
            float w = wr0c[k * 256 + h];
            float4 s = sp0_old[k];
            acc.x += w * s.x; acc.y += w * s.y; acc.z += w * s.z; acc.w += w * s.w;
        }
#pragma unroll 8
        for (int k = WR0C; k < 256; k++) {
            float w = __ldg(&wr0g[k * 256 + h]);
            float4 s = sp0_old[k];
            acc.x += w * s.x; acc.y += w * s.y; acc.z += w * s.z; acc.w += w * s.w;
        }
        m0.x = m0.x * ALPHA * (1.f - s0.x) + acc.x;
        m0.y = m0.y * ALPHA * (1.f - s0.y) + acc.y;
        m0.z = m0.z * ALPHA * (1.f - s0.z) + acc.z;
        m0.w = m0.w * ALPHA * (1.f - s0.w) + acc.w;
        s0.x = (m0.x - THRESH > 0.f) ? 1.f : 0.f;
        s0.y = (m0.y - THRESH > 0.f) ? 1.f : 0.f;
        s0.z = (m0.z - THRESH > 0.f) ? 1.f : 0.f;
        s0.w = (m0.w - THRESH > 0.f) ? 1.f : 0.f;
        sp0_new[h] = s0;
        __syncthreads();   // A: sp0_new visible

        // ================= layer 1 =================
        float4 acc1 = make_float4(bf1, bf1, bf1, bf1);
#pragma unroll 8
        for (int k = 0; k < WF1C; k++) {
            float w = wf1c[k * 256 + h];
            float4 s = sp0_new[k];
            acc1.x += w * s.x; acc1.y += w * s.y; acc1.z += w * s.z; acc1.w += w * s.w;
        }
#pragma unroll 8
        for (int k = WF1C; k < 256; k++) {
            float w = __ldg(&wf1g[k * 256 + h]);
            float4 s = sp0_new[k];
            acc1.x += w * s.x; acc1.y += w * s.y; acc1.z += w * s.z; acc1.w += w * s.w;
        }
#pragma unroll 8
        for (int k = 0; k < 256; k++) {
            float w = __ldg(&wr1g[k * 256 + h]);
            float4 s = sp1_old[k];
            acc1.x += w * s.x; acc1.y += w * s.y; acc1.z += w * s.z; acc1.w += w * s.w;
        }
        m1.x = m1.x * ALPHA * (1.f - s1v.x) + acc1.x;
        m1.y = m1.y * ALPHA * (1.f - s1v.y) + acc1.y;
        m1.z = m1.z * ALPHA * (1.f - s1v.z) + acc1.z;
        m1.w = m1.w * ALPHA * (1.f - s1v.w) + acc1.w;
        s1v.x = (m1.x - THRESH > 0.f) ? 1.f : 0.f;
        s1v.y = (m1.y - THRESH > 0.f) ? 1.f : 0.f;
        s1v.z = (m1.z - THRESH > 0.f) ? 1.f : 0.f;
        s1v.w = (m1.w - THRESH > 0.f) ? 1.f : 0.f;
        sp1_new[h] = s1v;
        __syncthreads();   // B: sp1_new visible

        // ================= output layer =================
        if (h < 160) {
            const float* spf = reinterpret_cast<const float*>(sp1_new);
            float oa = 0.f;
            int kbeg = phalf * 128;
#pragma unroll 8
            for (int k = kbeg; k < kbeg + 128; k++) {
                oa += spf[k * 4 + porow] * wot[k * 20 + pocol];
            }
            opart[h] = oa;
        }
        __syncthreads();
        if (h < 80) {
            float oa = opart[2 * h] + opart[2 * h + 1] + bov;
            o_mem = o_mem * ALPHA * (1.f - o_spk) + oa;
            o_spk = (o_mem - THRESH > 0.f) ? 1.f : 0.f;
            o_sumv += o_spk;
            osm[h] = o_mem;
        }
        __syncthreads();
        if (h < 4) {
            float mx = -1e30f;
#pragma unroll
            for (int o = 0; o < 20; o++) mx = fmaxf(mx, osm[h * 20 + o]);
            omax[h] = mx;
        }
        __syncthreads();
        if (h < 80) {
            otmp[h] = expf(o_mem - omax[orow]);
        }
        __syncthreads();
        if (h < 4) {
            float s = 0.f;
#pragma unroll
            for (int o = 0; o < 20; o++) s += otmp[h * 20 + o];
            osum[h] = s;
        }
        __syncthreads();
        if (h < 80) {
            o_mot += otmp[h] / osum[orow];
        }
        __syncthreads();
    }

    if (h < 80) {
        int b = b0 + orow;
        out[b * 20 + ocol] = o_sumv / (float)WIN;
        out[BATCH * 20 + b * 20 + ocol] = o_mot;
    }
}

// ---------------- launch ----------------
extern "C" void kernel_launch(void* const* d_in, const int* in_sizes, int n_in,
                              void* d_out, int out_size) {
    const float* x  = (const float*)d_in[0];
    const float* Wd = (const float*)d_in[1];
    const float* bd = (const float*)d_in[2];
    const float* Wf = (const float*)d_in[3];
    const float* bf = (const float*)d_in[4];
    const float* Wr = (const float*)d_in[5];
    const float* Wo = (const float*)d_in[6];
    const float* bo = (const float*)d_in[7];
    float* out = (float*)d_out;

    static bool attr_set = false;
    if (!attr_set) {
        cudaFuncSetAttribute(scan_kernel, cudaFuncAttributeMaxDynamicSharedMemorySize,
                             SCAN_SMEM_FLOATS * 4);
        attr_set = true;
    }

    prep_transpose<<<512, 256>>>(Wf, Wr, Wo);
    prep_wc<<<3 * NUM_INPUT, 256>>>(Wd);
    prep_cvec<<<1, 256>>>(bd, bf);
    gemm_ff0<<<dim3(NUM_HIDDEN / GB_BN, M_ROWS / GB_BM), 256>>>(x);
    scan_kernel<<<BATCH / SCAN_R, 256, SCAN_SMEM_FLOATS * 4>>>(bf, bo, out);
}

// round 3
// speedup vs baseline: 3.0873x; 1.4887x over previous
#include <cuda_runtime.h>

#define NUM_INPUT  700
#define NUM_HIDDEN 256
#define NUM_OUTPUT 20
#define WIN        50
#define BATCH      512
#define THRESH     0.3f
#define ALPHA      0.8f

#define M_ROWS (BATCH * WIN)   // 25600

typedef unsigned long long ull;

// ---------------- f32x2 helpers (sm_103a paired fp32) ----------------
__device__ __forceinline__ ull pack2(float x, float y) {
    ull r; asm("mov.b64 %0, {%1, %2};" : "=l"(r) : "f"(x), "f"(y)); return r;
}
__device__ __forceinline__ void unpack2(ull v, float& x, float& y) {
    asm("mov.b64 {%0, %1}, %2;" : "=f"(x), "=f"(y) : "l"(v));
}
__device__ __forceinline__ void ffma2(ull& d, ull a, ull b) {   // d = a*b + d
    asm("fma.rn.f32x2 %0, %1, %2, %0;" : "+l"(d) : "l"(a), "l"(b));
}
__device__ __forceinline__ ull fma2n(ull a, ull b, ull c) {     // a*b + c
    ull d; asm("fma.rn.f32x2 %0, %1, %2, %3;" : "=l"(d) : "l"(a), "l"(b), "l"(c)); return d;
}
__device__ __forceinline__ ull add2(ull a, ull b) {
    ull d; asm("add.rn.f32x2 %0, %1, %2;" : "=l"(d) : "l"(a), "l"(b)); return d;
}

// ---------------- device scratch ----------------
__device__ float g_WcT[3 * NUM_INPUT * NUM_HIDDEN];      // [i][k][h] combined Wf0 @ Wd[i], transposed
__device__ float g_WfT[2 * NUM_HIDDEN * NUM_HIDDEN];     // [l][k][h]
__device__ float g_WrT[2 * NUM_HIDDEN * NUM_HIDDEN];     // [l][k][h]
__device__ float g_WoT[NUM_HIDDEN * NUM_OUTPUT];         // [k][o]
__device__ float g_cvec[NUM_HIDDEN];
__device__ float g_ff0[M_ROWS * NUM_HIDDEN];             // [b*50+t][h]

// ---------------- prep kernels ----------------
__global__ void prep_transpose(const float* __restrict__ Wf,
                               const float* __restrict__ Wr,
                               const float* __restrict__ Wo) {
    int idx = blockIdx.x * 256 + threadIdx.x;
    if (idx < 2 * 256 * 256) {
        int h = idx & 255;
        int k = (idx >> 8) & 255;
        int l = idx >> 16;
        g_WfT[(l * 256 + k) * 256 + h] = Wf[(l * 256 + h) * 256 + k];
        g_WrT[(l * 256 + k) * 256 + h] = Wr[(l * 256 + h) * 256 + k];
    }
    if (idx < 256 * 20) {
        int o = idx % 20;
        int k = idx / 20;
        g_WoT[k * 20 + o] = Wo[o * 256 + k];
    }
}

__global__ void prep_wc(const float* __restrict__ Wd) {
    int ik = blockIdx.x;          // 0 .. 3*700-1
    int i = ik / NUM_INPUT;
    int k = ik % NUM_INPUT;
    int h = threadIdx.x;
    float s = 0.f;
#pragma unroll 8
    for (int j = 0; j < 256; j++) {
        s += g_WfT[j * 256 + h] * __ldg(&Wd[(i * 256 + j) * NUM_INPUT + k]);
    }
    g_WcT[(i * NUM_INPUT + k) * 256 + h] = s;
}

__global__ void prep_cvec(const float* __restrict__ bd, const float* __restrict__ bf) {
    int h = threadIdx.x;
    float s = bf[h];
#pragma unroll 8
    for (int j = 0; j < 256; j++) {
        float bsum = bd[j] + bd[256 + j] + bd[512 + j];
        s += bsum * g_WfT[j * 256 + h];
    }
    g_cvec[h] = s;
}

// ---------------- ff0 GEMM: M=25600, N=256, K=700 x 3 delays ----------------
// BM=128, BN=64, BK=16, 256 threads, 8x4 microtile via FFMA2 row-pairs.
#define GA_BM 128
#define GA_BN 64
#define GA_BK 16

__global__ __launch_bounds__(256) void gemm_ff0(const float* __restrict__ x) {
    __shared__ float As[GA_BK][GA_BM + 4];
    __shared__ float Bs[GA_BK][GA_BN];

    const int tid = threadIdx.x;
    const int rowBase = blockIdx.y * GA_BM;
    const int colBase = blockIdx.x * GA_BN;
    const int tx = tid & 15;       // col group (4 cols)
    const int ty = tid >> 4;       // row group (8 rows)

    // accp[p][j]: rows (2p, 2p+1), col j
    ull accp[4][4];
#pragma unroll
    for (int p = 0; p < 4; p++)
#pragma unroll
        for (int j = 0; j < 4; j++) accp[p][j] = 0ull;

    const int delays[3] = {0, 16, 32};

    const int mm = tid >> 2;            // 0..63
    const int kq = (tid & 3) * 4;       // 0,4,8,12
    const int kkB = tid >> 4;           // 0..15
    const int hhB = (tid & 15) * 4;

    for (int i = 0; i < 3; i++) {
        const int d = delays[i];
        const float* __restrict__ Bsrc = &g_WcT[i * NUM_INPUT * 256];

        for (int kb = 0; kb < 704; kb += GA_BK) {
            int kg = kb + kq;
            bool kvalid = (kg < NUM_INPUT);
#pragma unroll
            for (int half = 0; half < 2; half++) {
                int r = rowBase + mm + half * 64;
                int b = r / WIN;
                int t = r - b * WIN;
                int ts = t - d;
                float4 v = make_float4(0.f, 0.f, 0.f, 0.f);
                if (ts >= 0 && kvalid)
                    v = *reinterpret_cast<const float4*>(x + (b * WIN + ts) * NUM_INPUT + kg);
                As[kq + 0][mm + half * 64] = v.x;
                As[kq + 1][mm + half * 64] = v.y;
                As[kq + 2][mm + half * 64] = v.z;
                As[kq + 3][mm + half * 64] = v.w;
            }
            int kg2 = kb + kkB;
            float4 w = make_float4(0.f, 0.f, 0.f, 0.f);
            if (kg2 < NUM_INPUT)
                w = *reinterpret_cast<const float4*>(Bsrc + kg2 * 256 + colBase + hhB);
            *reinterpret_cast<float4*>(&Bs[kkB][hhB]) = w;

            __syncthreads();

#pragma unroll
            for (int kk = 0; kk < GA_BK; kk++) {
                ulonglong2 a0p = *reinterpret_cast<const ulonglong2*>(&As[kk][ty * 8 + 0]);
                ulonglong2 a1p = *reinterpret_cast<const ulonglong2*>(&As[kk][ty * 8 + 4]);
                float4 bb = *reinterpret_cast<const float4*>(&Bs[kk][tx * 4]);
                ull bp[4] = {pack2(bb.x, bb.x), pack2(bb.y, bb.y),
                             pack2(bb.z, bb.z), pack2(bb.w, bb.w)};
                ull ap[4] = {a0p.x, a0p.y, a1p.x, a1p.y};
#pragma unroll
                for (int p = 0; p < 4; p++)
#pragma unroll
                    for (int j = 0; j < 4; j++) ffma2(accp[p][j], ap[p], bp[j]);
            }
            __syncthreads();
        }
    }

#pragma unroll
    for (int p = 0; p < 4; p++) {
#pragma unroll
        for (int j = 0; j < 4; j++) {
            float v0, v1;
            unpack2(accp[p][j], v0, v1);
            int c = colBase + tx * 4 + j;
            int r0 = rowBase + ty * 8 + 2 * p;
            g_ff0[r0 * 256 + c] = v0 + g_cvec[c];
            g_ff0[(r0 + 1) * 256 + c] = v1 + g_cvec[c];
        }
    }
}

// ---------------- recurrent scan ----------------
// 64 blocks x 512 threads; each block owns 8 batch rows for all 50 steps.
// Thread = (h = tid&255, half = tid>>8). Each half sums half the k-range;
// partials exchanged through smem. Spikes stored [256][8] floats.
#define SCAN_R 8
#define C0H 32    // cached cols per half, layer0 Wr
#define C1H 32    // cached cols per half, layer1 Wf
#define C2H 12    // cached cols per half, layer1 Wr

// float offsets in dynamic smem (all multiples of 4 -> 16B aligned)
#define OFF_W    0                                  // (2*C0H + 2*C1H + 2*C2H)*256 = 152*256
#define N_WCOLS  (2*C0H + 2*C1H + 2*C2H)            // 152
#define OFF_WOT  (OFF_W + N_WCOLS * 256)            // 38912
#define OFF_SP0  (OFF_WOT + 256 * 20)               // 44032
#define OFF_SP1  (OFF_SP0 + 2 * 256 * 8)            // 48128
#define OFF_PART (OFF_SP1 + 2 * 256 * 8)            // 52224  (512 * ulonglong2)
#define OFF_OSM  (OFF_PART + 512 * 4)               // 54272
#define OFF_OTMP (OFF_OSM + 160)                    // 54432
#define SCAN_SMEM_FLOATS (OFF_OTMP + 160)           // 54592 -> 218368 bytes

// accumulate over one k-half: ncache cols from smem cache, rest from gmem
__device__ __forceinline__ void accum_half(ull acc[4],
                                           const float* __restrict__ wc,   // cache, col j -> k = kbeg + j
                                           const float* __restrict__ wg,   // gmem [k][h]
                                           const ulonglong2* __restrict__ sq, // spikes, elem k: sq[2k],sq[2k+1]
                                           int h, int kbeg, int ncache) {
#pragma unroll 4
    for (int j = 0; j < ncache; j++) {
        float w = wc[j * 256 + h];
        ull wp = pack2(w, w);
        ulonglong2 sa = sq[2 * (kbeg + j)];
        ulonglong2 sb = sq[2 * (kbeg + j) + 1];
        ffma2(acc[0], wp, sa.x); ffma2(acc[1], wp, sa.y);
        ffma2(acc[2], wp, sb.x); ffma2(acc[3], wp, sb.y);
    }
#pragma unroll 8
    for (int k = kbeg + ncache; k < kbeg + 128; k++) {
        float w = __ldg(wg + k * 256 + h);
        ull wp = pack2(w, w);
        ulonglong2 sa = sq[2 * k];
        ulonglong2 sb = sq[2 * k + 1];
        ffma2(acc[0], wp, sa.x); ffma2(acc[1], wp, sa.y);
        ffma2(acc[2], wp, sb.x); ffma2(acc[3], wp, sb.y);
    }
}

__global__ __launch_bounds__(512) void scan_kernel(const float* __restrict__ bf,
                                                   const float* __restrict__ bo,
                                                   float* __restrict__ out) {
    extern __shared__ float sm[];
    float* wcache = sm + OFF_W;
    float* wot    = sm + OFF_WOT;
    float* sp0f   = sm + OFF_SP0;     // [2][256][8]
    float* sp1f   = sm + OFF_SP1;
    ulonglong2* partq = reinterpret_cast<ulonglong2*>(sm + OFF_PART);
    float* opart  = sm + OFF_PART;    // reused (floats) for output partials
    float* osm    = sm + OFF_OSM;
    float* otmp   = sm + OFF_OTMP;

    const int tid = threadIdx.x;
    const int h = tid & 255;
    const int half = tid >> 8;
    const int b0 = blockIdx.x * SCAN_R;

    // ---- populate weight cache: per matrix, cols = first nH of each half's k-range ----
    for (int idx = tid; idx < N_WCOLS * 256; idx += 512) {
        int j = idx >> 8;
        int hh = idx & 255;
        const float* src;
        int k;
        if (j < 2 * C0H) {                 // layer0 Wr
            int j0 = j;
            k = (j0 < C0H) ? j0 : 128 + (j0 - C0H);
            src = g_WrT;
        } else if (j < 2 * C0H + 2 * C1H) { // layer1 Wf
            int j0 = j - 2 * C0H;
            k = (j0 < C1H) ? j0 : 128 + (j0 - C1H);
            src = g_WfT + 65536;
        } else {                            // layer1 Wr
            int j0 = j - 2 * C0H - 2 * C1H;
            k = (j0 < C2H) ? j0 : 128 + (j0 - C2H);
            src = g_WrT + 65536;
        }
        wcache[j * 256 + hh] = src[k * 256 + hh];
    }
    for (int idx = tid; idx < 256 * 20; idx += 512) wot[idx] = g_WoT[idx];
    for (int idx = tid; idx < 2 * 256 * 8; idx += 512) { sp0f[idx] = 0.f; sp1f[idx] = 0.f; }
    __syncthreads();

    // membrane state: this thread owns rows (half*4 .. half*4+3) -> 2 pairs
    ull m0a = 0, m0b = 0, m1a = 0, m1b = 0;
    const ull alpha2 = pack2(ALPHA, ALPHA);
    ull df0a = alpha2, df0b = alpha2, df1a = alpha2, df1b = alpha2;

    const float bf1 = bf[256 + h];
    const ull bf1p = pack2(bf1, bf1);

    // output-layer roles: tid<320 computes partials; tid<160 owns state
    const int r2 = (tid < 160) ? tid : tid - 160;
    const int orow = r2 / 20, ocol = r2 - orow * 20;
    const int okbeg = (tid < 160) ? 0 : 128;
    const float bov = (tid < 160) ? bo[ocol] : 0.f;
    float o_mem = 0.f, o_dfac = ALPHA, o_sumv = 0.f, o_mot = 0.f;

    const float* __restrict__ wr0g = g_WrT;
    const float* __restrict__ wf1g = g_WfT + 65536;
    const float* __restrict__ wr1g = g_WrT + 65536;
    const float* wc_wr0 = wcache + (half * C0H) * 256;
    const float* wc_wf1 = wcache + (2 * C0H + half * C1H) * 256;
    const float* wc_wr1 = wcache + (2 * C0H + 2 * C1H + half * C2H) * 256;

    const int kbeg = half * 128;
    const int myp = 2 * half;          // my row-pair indices: myp, myp+1
    const int otp = 2 * (1 - half);    // partner's pairs

    for (int t = 0; t < WIN; t++) {
        const int ri = t & 1;
        const int wi = 1 - ri;
        const ulonglong2* sq0_old = reinterpret_cast<const ulonglong2*>(sp0f + ri * 2048);
        const ulonglong2* sq0_new = reinterpret_cast<const ulonglong2*>(sp0f + wi * 2048);
        const ulonglong2* sq1_old = reinterpret_cast<const ulonglong2*>(sp1f + ri * 2048);
        float* sp0_new_f = sp0f + wi * 2048;
        float* sp1_new_f = sp1f + wi * 2048;

        // prefetch ff0 for my 4 rows (consumed after the k-loop)
        const float* f0p = g_ff0 + ((b0 + half * 4) * WIN + t) * 256 + h;
        float f00 = f0p[0];
        float f01 = f0p[WIN * 256];
        float f02 = f0p[2 * WIN * 256];
        float f03 = f0p[3 * WIN * 256];

        // ================= layer 0 =================
        ull acc[4] = {0ull, 0ull, 0ull, 0ull};
        accum_half(acc, wc_wr0, wr0g, sq0_old, h, kbeg, C0H);

        partq[tid] = make_ulonglong2(acc[otp], acc[otp + 1]);
        __syncthreads();
        {
            ulonglong2 pp = partq[tid ^ 256];
            ull a0 = add2(acc[myp], pp.x);
            ull a1 = add2(acc[myp + 1], pp.y);
            a0 = add2(a0, pack2(f00, f01));
            a1 = add2(a1, pack2(f02, f03));
            m0a = fma2n(m0a, df0a, a0);
            m0b = fma2n(m0b, df0b, a1);
            float mx, my, mz, mw;
            unpack2(m0a, mx, my); unpack2(m0b, mz, mw);
            float sx = (mx - THRESH > 0.f) ? 1.f : 0.f;
            float sy = (my - THRESH > 0.f) ? 1.f : 0.f;
            float sz = (mz - THRESH > 0.f) ? 1.f : 0.f;
            float sw = (mw - THRESH > 0.f) ? 1.f : 0.f;
            df0a = pack2(ALPHA * (1.f - sx), ALPHA * (1.f - sy));
            df0b = pack2(ALPHA * (1.f - sz), ALPHA * (1.f - sw));
            *reinterpret_cast<float4*>(sp0_new_f + h * 8 + half * 4) = make_float4(sx, sy, sz, sw);
        }
        __syncthreads();

        // ================= layer 1 =================
        acc[0] = acc[1] = acc[2] = acc[3] = 0ull;
        accum_half(acc, wc_wf1, wf1g, sq0_new, h, kbeg, C1H);
        accum_half(acc, wc_wr1, wr1g, sq1_old, h, kbeg, C2H);

        partq[tid] = make_ulonglong2(acc[otp], acc[otp + 1]);
        __syncthreads();
        {
            ulonglong2 pp = partq[tid ^ 256];
            ull a0 = add2(acc[myp], pp.x);
            ull a1 = add2(acc[myp + 1], pp.y);
            a0 = add2(a0, bf1p);
            a1 = add2(a1, bf1p);
            m1a = fma2n(m1a, df1a, a0);
            m1b = fma2n(m1b, df1b, a1);
            float mx, my, mz, mw;
            unpack2(m1a, mx, my); unpack2(m1b, mz, mw);
            float sx = (mx - THRESH > 0.f) ? 1.f : 0.f;
            float sy = (my - THRESH > 0.f) ? 1.f : 0.f;
            float sz = (mz - THRESH > 0.f) ? 1.f : 0.f;
            float sw = (mw - THRESH > 0.f) ? 1.f : 0.f;
            df1a = pack2(ALPHA * (1.f - sx), ALPHA * (1.f - sy));
            df1b = pack2(ALPHA * (1.f - sz), ALPHA * (1.f - sw));
            *reinterpret_cast<float4*>(sp1_new_f + h * 8 + half * 4) = make_float4(sx, sy, sz, sw);
        }
        __syncthreads();

        // ================= output layer =================
        if (tid < 320) {
            float oa = 0.f;
#pragma unroll 8
            for (int k = okbeg; k < okbeg + 128; k++) {
                oa += sp1_new_f[k * 8 + orow] * wot[k * 20 + ocol];
            }
            opart[tid] = oa;
        }
        __syncthreads();
        if (tid < 160) {
            float oa = opart[tid] + opart[tid + 160] + bov;
            o_mem = o_mem * o_dfac + oa;
            float os = (o_mem - THRESH > 0.f) ? 1.f : 0.f;
            o_dfac = ALPHA * (1.f - os);
            o_sumv += os;
            osm[tid] = o_mem;
        }
        __syncthreads();
        if (tid < 160) {
            float mx = -1e30f;
#pragma unroll
            for (int o = 0; o < 20; o++) mx = fmaxf(mx, osm[orow * 20 + o]);
            otmp[tid] = expf(o_mem - mx);
        }
        __syncthreads();
        if (tid < 160) {
            float s = 0.f;
#pragma unroll
            for (int o = 0; o < 20; o++) s += otmp[orow * 20 + o];
            o_mot += otmp[tid] / s;
        }
        __syncthreads();
    }

    if (tid < 160) {
        int b = b0 + orow;
        out[b * 20 + ocol] = o_sumv / (float)WIN;
        out[BATCH * 20 + b * 20 + ocol] = o_mot;
    }
}

// ---------------- launch ----------------
extern "C" void kernel_launch(void* const* d_in, const int* in_sizes, int n_in,
                              void* d_out, int out_size) {
    const float* x  = (const float*)d_in[0];
    const float* Wd = (const float*)d_in[1];
    const float* bd = (const float*)d_in[2];
    const float* Wf = (const float*)d_in[3];
    const float* bf = (const float*)d_in[4];
    const float* Wr = (const float*)d_in[5];
    const float* Wo = (const float*)d_in[6];
    const float* bo = (const float*)d_in[7];
    float* out = (float*)d_out;

    static bool attr_set = false;
    if (!attr_set) {
        cudaFuncSetAttribute(scan_kernel, cudaFuncAttributeMaxDynamicSharedMemorySize,
                             SCAN_SMEM_FLOATS * 4);
        attr_set = true;
    }

    prep_transpose<<<512, 256>>>(Wf, Wr, Wo);
    prep_wc<<<3 * NUM_INPUT, 256>>>(Wd);
    prep_cvec<<<1, 256>>>(bd, bf);
    gemm_ff0<<<dim3(NUM_HIDDEN / GA_BN, M_ROWS / GA_BM), 256>>>(x);
    scan_kernel<<<BATCH / SCAN_R, 512, SCAN_SMEM_FLOATS * 4>>>(bf, bo, out);
}